// round 12
// baseline (speedup 1.0000x reference)
#include <cuda_runtime.h>
#include <cuda_fp16.h>
#include <math.h>
#include <stdint.h>

#define CCH 512
#define HWT 4096
#define BATCH 2
#define NGROUPS 32
#define CPG 16

// ---------------- scratch (allocation-free) ----------------
__device__ __half  g_h[(size_t)BATCH * HWT * CCH];   // normalized, token-major
__device__ __half  g_q[(size_t)BATCH * HWT * CCH];
__device__ __half  g_k[(size_t)BATCH * HWT * CCH];
__device__ __half  g_v[(size_t)BATCH * CCH * HWT];   // channel-major
__device__ __half  g_o[(size_t)BATCH * HWT * CCH];   // attn out, token-major
__device__ __half  g_s[(size_t)BATCH * HWT * HWT];   // P = exp(logit)*2^-5, fp16
__device__ __half  g_w[4 * CCH * CCH];               // [q_w; k_w; v_w; p_w] fp16
__device__ float   g_bqkv[3 * CCH];                  // concat bias
__device__ float2  g_part[BATCH * NGROUPS * 4];      // GN partial {sum, sumsq}
__device__ float   g_rsp[(size_t)BATCH * HWT * 32];  // P row-sum partials per n-block

// ---------------- helpers ----------------
__device__ __forceinline__ uint32_t smem_u32(const void* p) {
    uint32_t a;
    asm("{ .reg .u64 t; cvta.to.shared.u64 t, %1; cvt.u32.u64 %0, t; }" : "=r"(a) : "l"(p));
    return a;
}
__device__ __forceinline__ void ldsm_x4(uint32_t& r0, uint32_t& r1, uint32_t& r2, uint32_t& r3,
                                        uint32_t addr) {
    asm volatile("ldmatrix.sync.aligned.m8n8.x4.shared.b16 {%0,%1,%2,%3}, [%4];"
                 : "=r"(r0), "=r"(r1), "=r"(r2), "=r"(r3) : "r"(addr));
}
__device__ __forceinline__ void mma_f16(float* c, const uint32_t* a, const uint32_t* b) {
    asm("mma.sync.aligned.m16n8k16.row.col.f32.f16.f16.f32 "
        "{%0,%1,%2,%3}, {%4,%5,%6,%7}, {%8,%9}, {%0,%1,%2,%3};"
        : "+f"(c[0]), "+f"(c[1]), "+f"(c[2]), "+f"(c[3])
        : "r"(a[0]), "r"(a[1]), "r"(a[2]), "r"(a[3]), "r"(b[0]), "r"(b[1]));
}

// ---------------- weight fp16 convert + bias concat ----------------
__global__ void w2h_kernel(const float* __restrict__ s0, const float* __restrict__ s1,
                           const float* __restrict__ s2, const float* __restrict__ s3,
                           __half* __restrict__ dst) {
    const int i = blockIdx.x * blockDim.x + threadIdx.x;
    const int N = CCH * CCH;
    dst[i]         = __float2half_rn(s0[i]);
    dst[i + N]     = __float2half_rn(s1[i]);
    dst[i + 2 * N] = __float2half_rn(s2[i]);
    dst[i + 3 * N] = __float2half_rn(s3[i]);
}
__global__ void bias_cat(const float* __restrict__ qb, const float* __restrict__ kb,
                         const float* __restrict__ vb, float* __restrict__ dst) {
    const int i = blockIdx.x * blockDim.x + threadIdx.x;
    const float* src = (i < CCH) ? qb : (i < 2 * CCH) ? kb : vb;
    dst[i] = src[i & (CCH - 1)];
}

// ---------------- GroupNorm partial sums (256 CTAs) ----------------
__global__ __launch_bounds__(256)
void gn_part(const float* __restrict__ x, float2* __restrict__ part) {
    const int pb = blockIdx.x;            // 0..255
    const int bg = pb >> 2, qt = pb & 3;
    const float4* xp = (const float4*)(x + (size_t)bg * CPG * HWT) + qt * (CPG * HWT / 16);
    const int N4 = CPG * HWT / 16;        // 4096 float4

    float s = 0.f, ss = 0.f;
    for (int i = threadIdx.x; i < N4; i += 256) {
        float4 v = xp[i];
        s  += v.x + v.y + v.z + v.w;
        ss += v.x * v.x + v.y * v.y + v.z * v.z + v.w * v.w;
    }
    __shared__ float rs[8], rss[8];
    #pragma unroll
    for (int o = 16; o > 0; o >>= 1) {
        s  += __shfl_xor_sync(~0u, s,  o);
        ss += __shfl_xor_sync(~0u, ss, o);
    }
    const int wid = threadIdx.x >> 5, lid = threadIdx.x & 31;
    if (lid == 0) { rs[wid] = s; rss[wid] = ss; }
    __syncthreads();
    if (threadIdx.x == 0) {
        float ts = 0.f, tss = 0.f;
        #pragma unroll
        for (int i = 0; i < 8; i++) { ts += rs[i]; tss += rss[i]; }
        part[pb] = make_float2(ts, tss);
    }
}

// ---------------- GN apply + transpose -> token-major fp16 h ----------------
__global__ __launch_bounds__(256)
void gn_apply_t(const float* __restrict__ x,
                const float* __restrict__ gw, const float* __restrict__ gb,
                const float2* __restrict__ part, __half* __restrict__ ht) {
    __shared__ float tile[64][65];
    __shared__ float2 stg[4];
    __shared__ float gwS[64], gbS[64];
    const int b = blockIdx.z;
    const int c0 = blockIdx.y * 64, t0 = blockIdx.x * 64;
    const float* xp = x + (size_t)b * CCH * HWT;
    __half* hp = ht + (size_t)b * HWT * CCH;
    const int tid = threadIdx.x;

    if (tid < 4) {
        const int g = b * NGROUPS + (c0 >> 4) + tid;
        float s = 0.f, ss = 0.f;
        #pragma unroll
        for (int q = 0; q < 4; q++) {
            float2 p = part[g * 4 + q];
            s += p.x; ss += p.y;
        }
        const float invN = 1.f / (float)(CPG * HWT);
        const float mean = s * invN;
        const float var  = fmaxf(ss * invN - mean * mean, 0.f);
        stg[tid] = make_float2(mean, rsqrtf(var + 1e-6f));
    }
    if (tid < 64) { gwS[tid] = gw[c0 + tid]; gbS[tid] = gb[c0 + tid]; }

    const int r = tid >> 2, q = tid & 3;
    const float4* xr = (const float4*)(xp + (size_t)(c0 + r) * HWT) + (t0 >> 2);
    #pragma unroll
    for (int i = 0; i < 4; i++) {
        float4 v = xr[q * 4 + i];
        tile[r][q * 16 + i * 4 + 0] = v.x;
        tile[r][q * 16 + i * 4 + 1] = v.y;
        tile[r][q * 16 + i * 4 + 2] = v.z;
        tile[r][q * 16 + i * 4 + 3] = v.w;
    }
    __syncthreads();

    #pragma unroll
    for (int p = 0; p < 4; p++) {
        const int tr = p * 16 + (tid >> 4);
        __half2* hrow = (__half2*)(hp + (size_t)(t0 + tr) * CCH + c0);
        #pragma unroll
        for (int qq = 0; qq < 2; qq++) {
            const int c2 = (tid & 15) + 16 * qq;
            const int cl0 = 2 * c2, cl1 = 2 * c2 + 1;
            const float2 mv0 = stg[cl0 >> 4];
            const float2 mv1 = stg[cl1 >> 4];
            const float a0 = mv0.y * gwS[cl0], b0 = gbS[cl0] - mv0.x * a0;
            const float a1 = mv1.y * gwS[cl1], b1 = gbS[cl1] - mv1.x * a1;
            hrow[c2] = __floats2half2_rn(tile[cl0][tr] * a0 + b0,
                                         tile[cl1][tr] * a1 + b1);
        }
    }
}

// ---------------- fp16 HMMA GEMM, CTA 128x128, 256 threads, 3-stage cp.async ----------------
// All epilogues smem-staged for coalesced 16B global stores.
// MODE 0: scores  -> half = exp(acc*scale)*2^-5; rowsum partials -> rsp
// MODE 1: qkv     -> q/k token-major (+bias); v segment transposed channel-major
// MODE 2: attn@V  -> half = acc / rowsum[m] (rowsum from rsp partials)
// MODE 3: proj    -> float = acc + bias[m] + res[m][n]
template<int MODE>
__global__ __launch_bounds__(256, 2)
void mma_gemm(const __half* __restrict__ A, const __half* __restrict__ B,
              const float* __restrict__ bias, const float* __restrict__ res,
              void* __restrict__ outv, __half* __restrict__ outK, __half* __restrict__ outV,
              float* __restrict__ rsp,
              int lda, int ldb, int ldo, int K, float scale,
              size_t sA, size_t sB, size_t sO, size_t sR) {
    constexpr int STG = 16384;           // 128 rows x 128B (BK=64 fp16)
    constexpr int NSTG = 3;
    extern __shared__ char smem[];       // [A0 A1 A2 | B0 B1 B2 | scratch 2KB]
    const uint32_t sb = smem_u32(smem);
    const uint32_t sbB = sb + NSTG * STG;
    float* scr = (float*)(smem + 2 * NSTG * STG);   // 2KB scratch (outside stage bufs)

    const int bz = blockIdx.z;
    A += (size_t)bz * sA;
    B += (size_t)bz * sB;
    if (MODE == 3) res += (size_t)bz * sR;
    if (MODE == 1) {
        outK += (size_t)bz * sO;
        outV += (size_t)bz * sO;
    }

    const int m0 = blockIdx.y * 128;
    const int n0 = blockIdx.x * 128;
    const int tid = threadIdx.x;
    const int lane = tid & 31;
    const int wid = tid >> 5;
    const int wm = wid & 1;              // 2 x 64 rows
    const int wn = wid >> 1;             // 4 x 32 cols

    // ---- cp.async geometry ----
    const int r0 = tid >> 3;             // 0..31
    const int cb = tid & 7;
    const __half* gA = A + (size_t)(m0 + r0) * lda + cb * 8;
    const __half* gB = B + (size_t)(n0 + r0) * ldb + cb * 8;
    uint32_t soff[4];
    #pragma unroll
    for (int it = 0; it < 4; it++) {
        const int row = r0 + 32 * it;
        soff[it] = (uint32_t)row * 128u + (uint32_t)((cb ^ (row & 7)) << 4);
    }

    // ---- ldmatrix geometry ----
    const int aRowB = wm * 64 + (lane & 15);
    const int aCk = (lane >> 4) & 1;
    const int bRowB = wn * 32 + (lane & 7) + (((lane >> 4) & 1) << 3);
    const int bCk = (lane >> 3) & 1;
    const int xr = lane & 7;

    float acc[4][4][4];
    #pragma unroll
    for (int mi = 0; mi < 4; mi++)
        #pragma unroll
        for (int ni = 0; ni < 4; ni++)
            #pragma unroll
            for (int r = 0; r < 4; r++) acc[mi][ni][r] = 0.f;

    auto load_tile = [&](int i, int s) {
        const __half* ga = gA + (size_t)i * 64;
        const __half* gb_ = gB + (size_t)i * 64;
        const uint32_t sa = sb + s * STG;
        const uint32_t sbb = sbB + s * STG;
        #pragma unroll
        for (int it = 0; it < 4; it++)
            asm volatile("cp.async.cg.shared.global [%0], [%1], 16;"
                :: "r"(sa + soff[it]), "l"(ga + (size_t)(32 * it) * lda) : "memory");
        #pragma unroll
        for (int it = 0; it < 4; it++)
            asm volatile("cp.async.cg.shared.global [%0], [%1], 16;"
                :: "r"(sbb + soff[it]), "l"(gb_ + (size_t)(32 * it) * ldb) : "memory");
    };

    const int NT = K / 64;
    load_tile(0, 0);
    asm volatile("cp.async.commit_group;" ::: "memory");
    load_tile(1, 1);
    asm volatile("cp.async.commit_group;" ::: "memory");

    int stage = 0;
    for (int i = 0; i < NT; i++) {
        asm volatile("cp.async.wait_group %0;" :: "n"(1) : "memory");
        __syncthreads();
        if (i + 2 < NT) {
            int s2 = stage + 2; if (s2 >= NSTG) s2 -= NSTG;
            load_tile(i + 2, s2);
        }
        asm volatile("cp.async.commit_group;" ::: "memory");

        const uint32_t saS = sb + stage * STG;
        const uint32_t sbS = sbB + stage * STG;
        #pragma unroll
        for (int t = 0; t < 4; t++) {
            uint32_t af[4][4], bf[4][2];
            #pragma unroll
            for (int mi = 0; mi < 4; mi++)
                ldsm_x4(af[mi][0], af[mi][1], af[mi][2], af[mi][3],
                        saS + (uint32_t)(aRowB + mi * 16) * 128u
                            + (uint32_t)(((2 * t + aCk) ^ xr) << 4));
            #pragma unroll
            for (int ni2 = 0; ni2 < 2; ni2++)
                ldsm_x4(bf[2 * ni2][0], bf[2 * ni2][1], bf[2 * ni2 + 1][0], bf[2 * ni2 + 1][1],
                        sbS + (uint32_t)(bRowB + ni2 * 16) * 128u
                            + (uint32_t)(((2 * t + bCk) ^ xr) << 4));
            #pragma unroll
            for (int mi = 0; mi < 4; mi++)
                #pragma unroll
                for (int ni = 0; ni < 4; ni++)
                    mma_f16(acc[mi][ni], af[mi], bf[ni]);
        }
        stage++; if (stage >= NSTG) stage -= NSTG;
    }

    // ---- drain pipeline; stage buffers become scratch ----
    asm volatile("cp.async.wait_group 0;" ::: "memory");

    // MODE 2: reduce rowsum partials into scr (outside stage bufs, safe pre-barrier)
    if (MODE == 2) {
        const int row = tid >> 1;                  // 0..127
        const float* rp = rsp + ((size_t)bz * HWT + m0 + row) * 32 + (tid & 1) * 16;
        float p = 0.f;
        #pragma unroll
        for (int j = 0; j < 16; j++) p += rp[j];
        p += __shfl_xor_sync(~0u, p, 1);
        if ((tid & 1) == 0) scr[row] = p;
    }
    __syncthreads();   // all mainloop smem reads done + scr visible

    // ---- MODE 1, v segment: smem-staged transpose for coalesced stores ----
    if (MODE == 1 && (n0 >> 9) == 2) {
        __half* st = (__half*)smem;
        constexpr int SSTR = 136;        // half stride, padded
        #pragma unroll
        for (int mi = 0; mi < 4; mi++) {
            const int rl0 = wm * 64 + mi * 16 + (lane >> 2);
            #pragma unroll
            for (int ni = 0; ni < 4; ni++) {
                const int ccl = wn * 32 + ni * 8 + 2 * (lane & 3);
                const int ccg = n0 + ccl;
                #pragma unroll
                for (int hf = 0; hf < 2; hf++) {
                    const int rl = rl0 + hf * 8;
                    st[ccl * SSTR + rl]       = __float2half_rn(acc[mi][ni][hf * 2 + 0] + bias[ccg]);
                    st[(ccl + 1) * SSTR + rl] = __float2half_rn(acc[mi][ni][hf * 2 + 1] + bias[ccg + 1]);
                }
            }
        }
        __syncthreads();
        const int nc0 = n0 - 1024;
        #pragma unroll
        for (int p = 0; p < 8; p++) {
            const int cl = p * 16 + (tid >> 4);
            __half2* orow = (__half2*)(outV + (size_t)(nc0 + cl) * HWT + m0);
            #pragma unroll
            for (int q = 0; q < 4; q++) {
                const int t2 = (tid & 15) + 16 * q;
                orow[t2] = *(__half2*)&st[cl * SSTR + 2 * t2];
            }
        }
        return;
    }

    // ---- staged epilogue ----
    if (MODE == 3) {
        // float tile, bias[m] folded at staging; residual added coalesced at storeback
        float* stf = (float*)smem;
        constexpr int SSTRF = 132;       // float stride, padded (66 KB < 96 KB)
        #pragma unroll
        for (int mi = 0; mi < 4; mi++) {
            const int rl0 = wm * 64 + mi * 16 + (lane >> 2);
            #pragma unroll
            for (int ni = 0; ni < 4; ni++) {
                const int ccl = wn * 32 + ni * 8 + 2 * (lane & 3);
                #pragma unroll
                for (int hf = 0; hf < 2; hf++) {
                    const int rl = rl0 + hf * 8;
                    const float bm = bias[m0 + rl];
                    float2 v;
                    v.x = acc[mi][ni][hf * 2 + 0] + bm;
                    v.y = acc[mi][ni][hf * 2 + 1] + bm;
                    *(float2*)&stf[rl * SSTRF + ccl] = v;
                }
            }
        }
        __syncthreads();
        const int row = tid >> 1, hc = tid & 1;
        float* oo = (float*)outv + (size_t)bz * sO;
        float4* orow = (float4*)(oo + (size_t)(m0 + row) * ldo + n0);
        const float4* rrow = (const float4*)(res + (size_t)(m0 + row) * ldo + n0);
        const float4* srow = (const float4*)&stf[row * SSTRF];
        #pragma unroll
        for (int i = 0; i < 16; i++) {
            const int idx = hc * 16 + i;
            float4 v = srow[idx];
            float4 rr = rrow[idx];
            v.x += rr.x; v.y += rr.y; v.z += rr.z; v.w += rr.w;
            orow[idx] = v;
        }
        return;
    }

    // half-output modes (0, 1 q/k, 2)
    __half* st = (__half*)smem;
    constexpr int SSTR = 136;            // half stride (conflict-free STS)
    float rloc[4][2];
    if (MODE == 0) {
        #pragma unroll
        for (int mi = 0; mi < 4; mi++) { rloc[mi][0] = 0.f; rloc[mi][1] = 0.f; }
    }
    #pragma unroll
    for (int mi = 0; mi < 4; mi++) {
        const int rl0 = wm * 64 + mi * 16 + (lane >> 2);
        #pragma unroll
        for (int ni = 0; ni < 4; ni++) {
            const int ccl = wn * 32 + ni * 8 + 2 * (lane & 3);
            #pragma unroll
            for (int hf = 0; hf < 2; hf++) {
                const int rl = rl0 + hf * 8;
                float vx = acc[mi][ni][hf * 2 + 0];
                float vy = acc[mi][ni][hf * 2 + 1];
                if (MODE == 0) {
                    vx = __expf(vx * scale) * 0.03125f;
                    vy = __expf(vy * scale) * 0.03125f;
                    rloc[mi][hf] += vx + vy;
                } else if (MODE == 1) {
                    vx += bias[n0 + ccl]; vy += bias[n0 + ccl + 1];
                } else {  // MODE 2
                    const float inv = 1.f / scr[rl];
                    vx *= inv; vy *= inv;
                }
                *(__half2*)&st[rl * SSTR + ccl] = __floats2half2_rn(vx, vy);
            }
        }
    }
    if (MODE == 0) {
        // reduce rowsum partials into scr (outside staged tile region? scr is at
        // smem+96KB, staged tile uses first 35KB — disjoint)
        #pragma unroll
        for (int mi = 0; mi < 4; mi++) {
            #pragma unroll
            for (int hf = 0; hf < 2; hf++) {
                float v = rloc[mi][hf];
                v += __shfl_xor_sync(~0u, v, 1);
                v += __shfl_xor_sync(~0u, v, 2);
                const int rl = wm * 64 + mi * 16 + (lane >> 2) + hf * 8;
                if ((lane & 3) == 0) scr[rl * 4 + wn] = v;
            }
        }
    }
    __syncthreads();

    // coalesced storeback: 2 threads per row, 8 x 16B each
    {
        const int row = tid >> 1, hc = tid & 1;
        __half* o;
        size_t rowoff;
        if (MODE == 0 || MODE == 2) {
            o = (__half*)outv + (size_t)bz * sO;
            rowoff = (size_t)(m0 + row) * ldo + n0;
        } else {  // MODE 1 q/k
            o = ((n0 >> 9) == 0) ? (__half*)outv + (size_t)bz * sO : outK;
            rowoff = (size_t)(m0 + row) * CCH + (n0 & (CCH - 1));
        }
        uint4* orow = (uint4*)(o + rowoff);
        const uint4* srow = (const uint4*)&st[row * SSTR];
        #pragma unroll
        for (int i = 0; i < 8; i++)
            orow[hc * 8 + i] = srow[hc * 8 + i];
    }
    if (MODE == 0 && tid < 128) {
        const float t = scr[tid * 4 + 0] + scr[tid * 4 + 1]
                      + scr[tid * 4 + 2] + scr[tid * 4 + 3];
        rsp[((size_t)bz * HWT + m0 + tid) * 32 + blockIdx.x] = t;
    }
}

// ---------------- launch ----------------
extern "C" void kernel_launch(void* const* d_in, const int* in_sizes, int n_in,
                              void* d_out, int out_size) {
    const float* x    = (const float*)d_in[0];
    const float* gn_w = (const float*)d_in[1];
    const float* gn_b = (const float*)d_in[2];
    const float* q_w  = (const float*)d_in[3];
    const float* q_b  = (const float*)d_in[4];
    const float* k_w  = (const float*)d_in[5];
    const float* k_b  = (const float*)d_in[6];
    const float* v_w  = (const float*)d_in[7];
    const float* v_b  = (const float*)d_in[8];
    const float* p_w  = (const float*)d_in[9];
    const float* p_b  = (const float*)d_in[10];
    float* out = (float*)d_out;

    __half *h, *q, *k, *v, *o, *s, *w;
    float *bq, *rsp;
    float2* part;
    cudaGetSymbolAddress((void**)&h, g_h);
    cudaGetSymbolAddress((void**)&q, g_q);
    cudaGetSymbolAddress((void**)&k, g_k);
    cudaGetSymbolAddress((void**)&v, g_v);
    cudaGetSymbolAddress((void**)&o, g_o);
    cudaGetSymbolAddress((void**)&s, g_s);
    cudaGetSymbolAddress((void**)&w, g_w);
    cudaGetSymbolAddress((void**)&bq, g_bqkv);
    cudaGetSymbolAddress((void**)&rsp, g_rsp);
    cudaGetSymbolAddress((void**)&part, g_part);

    const int SMEM_T = 3 * 2 * 16384 + 2048;   // 100352
    cudaFuncSetAttribute(mma_gemm<0>, cudaFuncAttributeMaxDynamicSharedMemorySize, SMEM_T);
    cudaFuncSetAttribute(mma_gemm<1>, cudaFuncAttributeMaxDynamicSharedMemorySize, SMEM_T);
    cudaFuncSetAttribute(mma_gemm<2>, cudaFuncAttributeMaxDynamicSharedMemorySize, SMEM_T);
    cudaFuncSetAttribute(mma_gemm<3>, cudaFuncAttributeMaxDynamicSharedMemorySize, SMEM_T);

    const size_t TOK = (size_t)HWT * CCH;
    const size_t SS  = (size_t)HWT * HWT;
    const size_t CHW = (size_t)CCH * HWT;
    const int WN = CCH * CCH;
    const float att_scale = 0.04419417382415922f; // 1/sqrt(512)

    // 0. weights -> fp16 (concat [q;k;v;p]), bias concat
    w2h_kernel<<<WN / 256, 256>>>(q_w, k_w, v_w, p_w, w);
    bias_cat<<<3 * CCH / 256, 256>>>(q_b, k_b, v_b, bq);
    __half* pw = w + 3 * WN;

    // 1. GroupNorm partials + apply/transpose -> h token-major fp16
    gn_part<<<BATCH * NGROUPS * 4, 256>>>(x, part);
    gn_apply_t<<<dim3(HWT / 64, CCH / 64, BATCH), 256>>>(x, gn_w, gn_b, part, h);

    // 2. fused qkv: M=HW, N=1536, K=512; v written channel-major transposed
    dim3 gq(3 * CCH / 128, HWT / 128, BATCH);
    mma_gemm<1><<<gq, 256, SMEM_T>>>(h, w, bq, nullptr, q, k, v, nullptr,
        CCH, CCH, CCH, CCH, 1.f, TOK, 0, TOK, 0);

    // 3. P = exp(scale * Q@K^T)*2^-5 : M=N=HW, K=C; rowsum partials -> rsp
    dim3 gs(HWT / 128, HWT / 128, BATCH);
    mma_gemm<0><<<gs, 256, SMEM_T>>>(q, k, nullptr, nullptr, s, nullptr, nullptr, rsp,
        CCH, CCH, HWT, CCH, att_scale, TOK, TOK, SS, 0);

    // 4. o = (P@V) / rowsum(P) : M=HW, N=C, K=HW
    dim3 ga(CCH / 128, HWT / 128, BATCH);
    mma_gemm<2><<<ga, 256, SMEM_T>>>(s, v, nullptr, nullptr, o, nullptr, nullptr, rsp,
        HWT, HWT, CCH, HWT, 1.f, SS, TOK, TOK, 0);

    // 5. out = x + P_w @ o^T (channel-major): M=C, N=HW, K=C
    dim3 gp(HWT / 128, CCH / 128, BATCH);
    mma_gemm<3><<<gp, 256, SMEM_T>>>(pw, o, p_b, x, out, nullptr, nullptr, nullptr,
        CCH, CCH, HWT, CCH, 1.f, 0, TOK, CHW, CHW);
}

// round 13
// speedup vs baseline: 1.1320x; 1.1320x over previous
#include <cuda_runtime.h>
#include <cuda_fp16.h>
#include <math.h>
#include <stdint.h>

#define CCH 512
#define HWT 4096
#define BATCH 2
#define NGROUPS 32
#define CPG 16

// ---------------- scratch (allocation-free) ----------------
__device__ __half  g_h[(size_t)BATCH * HWT * CCH];   // normalized, token-major
__device__ __half  g_q[(size_t)BATCH * HWT * CCH];
__device__ __half  g_k[(size_t)BATCH * HWT * CCH];
__device__ __half  g_v[(size_t)BATCH * CCH * HWT];   // channel-major
__device__ __half  g_o[(size_t)BATCH * HWT * CCH];   // attn out, token-major
__device__ __half  g_s[(size_t)BATCH * HWT * HWT];   // P = 2^(logit*log2e-5), fp16
__device__ __half  g_w[4 * CCH * CCH];               // [q_w; k_w; v_w; p_w] fp16
__device__ float   g_bqkv[3 * CCH];                  // concat bias
__device__ float2  g_part[BATCH * NGROUPS * 4];      // GN partial {sum, sumsq}

// ---------------- helpers ----------------
__device__ __forceinline__ uint32_t smem_u32(const void* p) {
    uint32_t a;
    asm("{ .reg .u64 t; cvta.to.shared.u64 t, %1; cvt.u32.u64 %0, t; }" : "=r"(a) : "l"(p));
    return a;
}
__device__ __forceinline__ void ldsm_x4(uint32_t& r0, uint32_t& r1, uint32_t& r2, uint32_t& r3,
                                        uint32_t addr) {
    asm volatile("ldmatrix.sync.aligned.m8n8.x4.shared.b16 {%0,%1,%2,%3}, [%4];"
                 : "=r"(r0), "=r"(r1), "=r"(r2), "=r"(r3) : "r"(addr));
}
__device__ __forceinline__ void mma_f16(float* c, const uint32_t* a, const uint32_t* b) {
    asm("mma.sync.aligned.m16n8k16.row.col.f32.f16.f16.f32 "
        "{%0,%1,%2,%3}, {%4,%5,%6,%7}, {%8,%9}, {%0,%1,%2,%3};"
        : "+f"(c[0]), "+f"(c[1]), "+f"(c[2]), "+f"(c[3])
        : "r"(a[0]), "r"(a[1]), "r"(a[2]), "r"(a[3]), "r"(b[0]), "r"(b[1]));
}

// ---------------- weight fp16 convert + bias concat ----------------
__global__ void w2h_kernel(const float* __restrict__ s0, const float* __restrict__ s1,
                           const float* __restrict__ s2, const float* __restrict__ s3,
                           __half* __restrict__ dst) {
    const int i = blockIdx.x * blockDim.x + threadIdx.x;
    const int N = CCH * CCH;
    dst[i]         = __float2half_rn(s0[i]);
    dst[i + N]     = __float2half_rn(s1[i]);
    dst[i + 2 * N] = __float2half_rn(s2[i]);
    dst[i + 3 * N] = __float2half_rn(s3[i]);
}
__global__ void bias_cat(const float* __restrict__ qb, const float* __restrict__ kb,
                         const float* __restrict__ vb, float* __restrict__ dst) {
    const int i = blockIdx.x * blockDim.x + threadIdx.x;
    const float* src = (i < CCH) ? qb : (i < 2 * CCH) ? kb : vb;
    dst[i] = src[i & (CCH - 1)];
}

// ---------------- GroupNorm partial sums (256 CTAs) ----------------
__global__ __launch_bounds__(256)
void gn_part(const float* __restrict__ x, float2* __restrict__ part) {
    const int pb = blockIdx.x;            // 0..255
    const int bg = pb >> 2, qt = pb & 3;
    const float4* xp = (const float4*)(x + (size_t)bg * CPG * HWT) + qt * (CPG * HWT / 16);
    const int N4 = CPG * HWT / 16;        // 4096 float4

    float s = 0.f, ss = 0.f;
    for (int i = threadIdx.x; i < N4; i += 256) {
        float4 v = xp[i];
        s  += v.x + v.y + v.z + v.w;
        ss += v.x * v.x + v.y * v.y + v.z * v.z + v.w * v.w;
    }
    __shared__ float rs[8], rss[8];
    #pragma unroll
    for (int o = 16; o > 0; o >>= 1) {
        s  += __shfl_xor_sync(~0u, s,  o);
        ss += __shfl_xor_sync(~0u, ss, o);
    }
    const int wid = threadIdx.x >> 5, lid = threadIdx.x & 31;
    if (lid == 0) { rs[wid] = s; rss[wid] = ss; }
    __syncthreads();
    if (threadIdx.x == 0) {
        float ts = 0.f, tss = 0.f;
        #pragma unroll
        for (int i = 0; i < 8; i++) { ts += rs[i]; tss += rss[i]; }
        part[pb] = make_float2(ts, tss);
    }
}

// ---------------- GN apply + transpose -> token-major fp16 h ----------------
__global__ __launch_bounds__(256)
void gn_apply_t(const float* __restrict__ x,
                const float* __restrict__ gw, const float* __restrict__ gb,
                const float2* __restrict__ part, __half* __restrict__ ht) {
    __shared__ float tile[64][65];
    __shared__ float2 stg[4];
    __shared__ float gwS[64], gbS[64];
    const int b = blockIdx.z;
    const int c0 = blockIdx.y * 64, t0 = blockIdx.x * 64;
    const float* xp = x + (size_t)b * CCH * HWT;
    __half* hp = ht + (size_t)b * HWT * CCH;
    const int tid = threadIdx.x;

    if (tid < 4) {
        const int g = b * NGROUPS + (c0 >> 4) + tid;
        float s = 0.f, ss = 0.f;
        #pragma unroll
        for (int q = 0; q < 4; q++) {
            float2 p = part[g * 4 + q];
            s += p.x; ss += p.y;
        }
        const float invN = 1.f / (float)(CPG * HWT);
        const float mean = s * invN;
        const float var  = fmaxf(ss * invN - mean * mean, 0.f);
        stg[tid] = make_float2(mean, rsqrtf(var + 1e-6f));
    }
    if (tid < 64) { gwS[tid] = gw[c0 + tid]; gbS[tid] = gb[c0 + tid]; }

    const int r = tid >> 2, q = tid & 3;
    const float4* xr = (const float4*)(xp + (size_t)(c0 + r) * HWT) + (t0 >> 2);
    #pragma unroll
    for (int i = 0; i < 4; i++) {
        float4 v = xr[q * 4 + i];
        tile[r][q * 16 + i * 4 + 0] = v.x;
        tile[r][q * 16 + i * 4 + 1] = v.y;
        tile[r][q * 16 + i * 4 + 2] = v.z;
        tile[r][q * 16 + i * 4 + 3] = v.w;
    }
    __syncthreads();

    #pragma unroll
    for (int p = 0; p < 4; p++) {
        const int tr = p * 16 + (tid >> 4);
        __half2* hrow = (__half2*)(hp + (size_t)(t0 + tr) * CCH + c0);
        #pragma unroll
        for (int qq = 0; qq < 2; qq++) {
            const int c2 = (tid & 15) + 16 * qq;
            const int cl0 = 2 * c2, cl1 = 2 * c2 + 1;
            const float2 mv0 = stg[cl0 >> 4];
            const float2 mv1 = stg[cl1 >> 4];
            const float a0 = mv0.y * gwS[cl0], b0 = gbS[cl0] - mv0.x * a0;
            const float a1 = mv1.y * gwS[cl1], b1 = gbS[cl1] - mv1.x * a1;
            hrow[c2] = __floats2half2_rn(tile[cl0][tr] * a0 + b0,
                                         tile[cl1][tr] * a1 + b1);
        }
    }
}

// ---------------- fp16 HMMA GEMM, CTA 128x128, 3-stage cp.async (R8 proven) ----------------
// MODE 0: scores  -> out half2 = ex2.approx.f16x2(acc*scale*log2e - 5)
// MODE 1: qkv     -> seg by n0: q/k token-major (+bias); v seg smem-staged transpose
// MODE 2: attn@V  -> rowsum of A tiles, out half = acc / rowsum[m]
// MODE 3: proj    -> out float = acc + bias[m] + res[m][n]
template<int MODE>
__global__ __launch_bounds__(256, 2)
void mma_gemm(const __half* __restrict__ A, const __half* __restrict__ B,
              const float* __restrict__ bias, const float* __restrict__ res,
              void* __restrict__ outv, __half* __restrict__ outK, __half* __restrict__ outV,
              int lda, int ldb, int ldo, int K, float scale,
              size_t sA, size_t sB, size_t sO, size_t sR) {
    constexpr int STG = 16384;           // 128 rows x 128B (BK=64 fp16)
    constexpr int NSTG = 3;
    extern __shared__ char smem[];       // [A0 A1 A2 | B0 B1 B2 | rowsum]
    const uint32_t sb = smem_u32(smem);
    const uint32_t sbB = sb + NSTG * STG;
    float* rs_s = (float*)(smem + 2 * NSTG * STG);

    const int bz = blockIdx.z;
    A += (size_t)bz * sA;
    B += (size_t)bz * sB;
    if (MODE == 3) res += (size_t)bz * sR;
    if (MODE == 1) {
        outK += (size_t)bz * sO;
        outV += (size_t)bz * sO;
    }

    const int m0 = blockIdx.y * 128;
    const int n0 = blockIdx.x * 128;
    const int tid = threadIdx.x;
    const int lane = tid & 31;
    const int wid = tid >> 5;
    const int wm = wid & 1;              // 2 x 64 rows
    const int wn = wid >> 1;             // 4 x 32 cols

    // ---- cp.async geometry ----
    const int r0 = tid >> 3;             // 0..31
    const int cb = tid & 7;
    const __half* gA = A + (size_t)(m0 + r0) * lda + cb * 8;
    const __half* gB = B + (size_t)(n0 + r0) * ldb + cb * 8;
    uint32_t soff[4];
    #pragma unroll
    for (int it = 0; it < 4; it++) {
        const int row = r0 + 32 * it;
        soff[it] = (uint32_t)row * 128u + (uint32_t)((cb ^ (row & 7)) << 4);
    }

    // ---- ldmatrix geometry ----
    const int aRowB = wm * 64 + (lane & 15);
    const int aCk = (lane >> 4) & 1;
    const int bRowB = wn * 32 + (lane & 7) + (((lane >> 4) & 1) << 3);
    const int bCk = (lane >> 3) & 1;
    const int xr = lane & 7;

    // ---- rowsum geometry (MODE 2) ----
    const int srow = tid >> 1;           // 0..127
    const int shalf = tid & 1;
    uint32_t rsoff[4];
    if (MODE == 2) {
        #pragma unroll
        for (int c4 = 0; c4 < 4; c4++) {
            const int ch = shalf * 4 + c4;
            rsoff[c4] = (uint32_t)srow * 128u + (uint32_t)((ch ^ (srow & 7)) << 4);
        }
    }
    float rsum = 0.f;

    float acc[4][4][4];
    #pragma unroll
    for (int mi = 0; mi < 4; mi++)
        #pragma unroll
        for (int ni = 0; ni < 4; ni++)
            #pragma unroll
            for (int r = 0; r < 4; r++) acc[mi][ni][r] = 0.f;

    auto load_tile = [&](int i, int s) {
        const __half* ga = gA + (size_t)i * 64;
        const __half* gb_ = gB + (size_t)i * 64;
        const uint32_t sa = sb + s * STG;
        const uint32_t sbb = sbB + s * STG;
        #pragma unroll
        for (int it = 0; it < 4; it++)
            asm volatile("cp.async.cg.shared.global [%0], [%1], 16;"
                :: "r"(sa + soff[it]), "l"(ga + (size_t)(32 * it) * lda) : "memory");
        #pragma unroll
        for (int it = 0; it < 4; it++)
            asm volatile("cp.async.cg.shared.global [%0], [%1], 16;"
                :: "r"(sbb + soff[it]), "l"(gb_ + (size_t)(32 * it) * ldb) : "memory");
    };

    const int NT = K / 64;
    load_tile(0, 0);
    asm volatile("cp.async.commit_group;" ::: "memory");
    load_tile(1, 1);
    asm volatile("cp.async.commit_group;" ::: "memory");

    int stage = 0;
    for (int i = 0; i < NT; i++) {
        asm volatile("cp.async.wait_group %0;" :: "n"(1) : "memory");
        __syncthreads();
        if (i + 2 < NT) {
            int s2 = stage + 2; if (s2 >= NSTG) s2 -= NSTG;
            load_tile(i + 2, s2);
        }
        asm volatile("cp.async.commit_group;" ::: "memory");

        if (MODE == 2) {
            // accumulate row sums of this A tile (P values)
            const char* base = smem + stage * STG;
            #pragma unroll
            for (int c4 = 0; c4 < 4; c4++) {
                uint4 d = *(const uint4*)(base + rsoff[c4]);
                float2 f0 = __half22float2(*(__half2*)&d.x);
                float2 f1 = __half22float2(*(__half2*)&d.y);
                float2 f2 = __half22float2(*(__half2*)&d.z);
                float2 f3 = __half22float2(*(__half2*)&d.w);
                rsum += (f0.x + f0.y) + (f1.x + f1.y) + (f2.x + f2.y) + (f3.x + f3.y);
            }
        }

        const uint32_t saS = sb + stage * STG;
        const uint32_t sbS = sbB + stage * STG;
        #pragma unroll
        for (int t = 0; t < 4; t++) {
            uint32_t af[4][4], bf[4][2];
            #pragma unroll
            for (int mi = 0; mi < 4; mi++)
                ldsm_x4(af[mi][0], af[mi][1], af[mi][2], af[mi][3],
                        saS + (uint32_t)(aRowB + mi * 16) * 128u
                            + (uint32_t)(((2 * t + aCk) ^ xr) << 4));
            #pragma unroll
            for (int ni2 = 0; ni2 < 2; ni2++)
                ldsm_x4(bf[2 * ni2][0], bf[2 * ni2][1], bf[2 * ni2 + 1][0], bf[2 * ni2 + 1][1],
                        sbS + (uint32_t)(bRowB + ni2 * 16) * 128u
                            + (uint32_t)(((2 * t + bCk) ^ xr) << 4));
            #pragma unroll
            for (int mi = 0; mi < 4; mi++)
                #pragma unroll
                for (int ni = 0; ni < 4; ni++)
                    mma_f16(acc[mi][ni], af[mi], bf[ni]);
        }
        stage++; if (stage >= NSTG) stage -= NSTG;
    }

    if (MODE == 2) {
        rsum += __shfl_xor_sync(~0u, rsum, 1);
        rs_s[srow] = rsum;               // both halves write same value
        __syncthreads();
    }

    // ---- MODE 1, v segment: smem-staged transpose for coalesced stores ----
    if (MODE == 1 && (n0 >> 9) == 2) {
        asm volatile("cp.async.wait_group 0;" ::: "memory");
        __syncthreads();
        __half* st = (__half*)smem;
        constexpr int SSTR = 136;        // half stride, padded
        #pragma unroll
        for (int mi = 0; mi < 4; mi++) {
            const int rl0 = wm * 64 + mi * 16 + (lane >> 2);
            #pragma unroll
            for (int ni = 0; ni < 4; ni++) {
                const int ccl = wn * 32 + ni * 8 + 2 * (lane & 3);
                const int ccg = n0 + ccl;
                #pragma unroll
                for (int hf = 0; hf < 2; hf++) {
                    const int rl = rl0 + hf * 8;
                    st[ccl * SSTR + rl]       = __float2half_rn(acc[mi][ni][hf * 2 + 0] + bias[ccg]);
                    st[(ccl + 1) * SSTR + rl] = __float2half_rn(acc[mi][ni][hf * 2 + 1] + bias[ccg + 1]);
                }
            }
        }
        __syncthreads();
        const int nc0 = n0 - 1024;
        #pragma unroll
        for (int p = 0; p < 8; p++) {
            const int cl = p * 16 + (tid >> 4);
            __half2* orow = (__half2*)(outV + (size_t)(nc0 + cl) * HWT + m0);
            #pragma unroll
            for (int q = 0; q < 4; q++) {
                const int t2 = (tid & 15) + 16 * q;
                orow[t2] = *(__half2*)&st[cl * SSTR + 2 * t2];
            }
        }
        return;
    }

    // ---- epilogue ----
    const float c1 = scale * 1.4426950408889634f;   // scale * log2(e)
    #pragma unroll
    for (int mi = 0; mi < 4; mi++) {
        const int rl0 = wm * 64 + mi * 16 + (lane >> 2);
        #pragma unroll
        for (int ni = 0; ni < 4; ni++) {
            const int ccg = n0 + wn * 32 + ni * 8 + 2 * (lane & 3);
            #pragma unroll
            for (int hf = 0; hf < 2; hf++) {
                const int rl = rl0 + hf * 8;
                const int r = m0 + rl;
                float vx = acc[mi][ni][hf * 2 + 0];
                float vy = acc[mi][ni][hf * 2 + 1];
                if (MODE == 0) {
                    // P = 2^(logit*log2e - 5)  via f16x2 MUFU (2 vals/op)
                    const float yx = fmaf(vx, c1, -5.0f);
                    const float yy = fmaf(vy, c1, -5.0f);
                    uint32_t h2, p2;
                    asm("cvt.rn.f16x2.f32 %0, %1, %2;" : "=r"(h2) : "f"(yy), "f"(yx));
                    asm("ex2.approx.f16x2 %0, %1;" : "=r"(p2) : "r"(h2));
                    __half* o = (__half*)outv + (size_t)bz * sO;
                    *(uint32_t*)(o + (size_t)r * ldo + ccg) = p2;
                } else if (MODE == 1) {
                    vx += bias[ccg]; vy += bias[ccg + 1];
                    const int nc = ccg & (CCH - 1);
                    __half* o = ((n0 >> 9) == 0) ? (__half*)outv + (size_t)bz * sO : outK;
                    *(__half2*)(o + (size_t)r * CCH + nc) = __floats2half2_rn(vx, vy);
                } else if (MODE == 2) {
                    const float inv = 1.f / rs_s[rl];
                    __half* o = (__half*)outv + (size_t)bz * sO;
                    *(__half2*)(o + (size_t)r * ldo + ccg) =
                        __floats2half2_rn(vx * inv, vy * inv);
                } else {
                    const float bm = bias[r];
                    float2 rr = *(const float2*)&res[(size_t)r * ldo + ccg];
                    float* o = (float*)outv + (size_t)bz * sO;
                    float2 v; v.x = vx + bm + rr.x; v.y = vy + bm + rr.y;
                    *(float2*)(o + (size_t)r * ldo + ccg) = v;
                }
            }
        }
    }
}

// ---------------- launch ----------------
extern "C" void kernel_launch(void* const* d_in, const int* in_sizes, int n_in,
                              void* d_out, int out_size) {
    const float* x    = (const float*)d_in[0];
    const float* gn_w = (const float*)d_in[1];
    const float* gn_b = (const float*)d_in[2];
    const float* q_w  = (const float*)d_in[3];
    const float* q_b  = (const float*)d_in[4];
    const float* k_w  = (const float*)d_in[5];
    const float* k_b  = (const float*)d_in[6];
    const float* v_w  = (const float*)d_in[7];
    const float* v_b  = (const float*)d_in[8];
    const float* p_w  = (const float*)d_in[9];
    const float* p_b  = (const float*)d_in[10];
    float* out = (float*)d_out;

    __half *h, *q, *k, *v, *o, *s, *w;
    float *bq;
    float2* part;
    cudaGetSymbolAddress((void**)&h, g_h);
    cudaGetSymbolAddress((void**)&q, g_q);
    cudaGetSymbolAddress((void**)&k, g_k);
    cudaGetSymbolAddress((void**)&v, g_v);
    cudaGetSymbolAddress((void**)&o, g_o);
    cudaGetSymbolAddress((void**)&s, g_s);
    cudaGetSymbolAddress((void**)&w, g_w);
    cudaGetSymbolAddress((void**)&bq, g_bqkv);
    cudaGetSymbolAddress((void**)&part, g_part);

    const int SMEM_T = 3 * 2 * 16384 + 512;   // 98816
    cudaFuncSetAttribute(mma_gemm<0>, cudaFuncAttributeMaxDynamicSharedMemorySize, SMEM_T);
    cudaFuncSetAttribute(mma_gemm<1>, cudaFuncAttributeMaxDynamicSharedMemorySize, SMEM_T);
    cudaFuncSetAttribute(mma_gemm<2>, cudaFuncAttributeMaxDynamicSharedMemorySize, SMEM_T);
    cudaFuncSetAttribute(mma_gemm<3>, cudaFuncAttributeMaxDynamicSharedMemorySize, SMEM_T);

    const size_t TOK = (size_t)HWT * CCH;
    const size_t SS  = (size_t)HWT * HWT;
    const size_t CHW = (size_t)CCH * HWT;
    const int WN = CCH * CCH;
    const float att_scale = 0.04419417382415922f; // 1/sqrt(512)

    // 0. weights -> fp16 (concat [q;k;v;p]), bias concat
    w2h_kernel<<<WN / 256, 256>>>(q_w, k_w, v_w, p_w, w);
    bias_cat<<<3 * CCH / 256, 256>>>(q_b, k_b, v_b, bq);
    __half* pw = w + 3 * WN;

    // 1. GroupNorm partials + apply/transpose -> h token-major fp16
    gn_part<<<BATCH * NGROUPS * 4, 256>>>(x, part);
    gn_apply_t<<<dim3(HWT / 64, CCH / 64, BATCH), 256>>>(x, gn_w, gn_b, part, h);

    // 2. fused qkv: M=HW, N=1536, K=512; v written channel-major transposed
    dim3 gq(3 * CCH / 128, HWT / 128, BATCH);
    mma_gemm<1><<<gq, 256, SMEM_T>>>(h, w, bq, nullptr, q, k, v,
        CCH, CCH, CCH, CCH, 1.f, TOK, 0, TOK, 0);

    // 3. P = 2^(scale*log2e * Q@K^T - 5) : M=N=HW, K=C
    dim3 gs(HWT / 128, HWT / 128, BATCH);
    mma_gemm<0><<<gs, 256, SMEM_T>>>(q, k, nullptr, nullptr, s, nullptr, nullptr,
        CCH, CCH, HWT, CCH, att_scale, TOK, TOK, SS, 0);

    // 4. o = (P@V) / rowsum(P) : M=HW, N=C, K=HW
    dim3 ga(CCH / 128, HWT / 128, BATCH);
    mma_gemm<2><<<ga, 256, SMEM_T>>>(s, v, nullptr, nullptr, o, nullptr, nullptr,
        HWT, HWT, CCH, HWT, 1.f, SS, TOK, TOK, 0);

    // 5. out = x + P_w @ o^T (channel-major): M=C, N=HW, K=C
    dim3 gp(HWT / 128, CCH / 128, BATCH);
    mma_gemm<3><<<gp, 256, SMEM_T>>>(pw, o, p_b, x, out, nullptr, nullptr,
        CCH, CCH, HWT, CCH, 1.f, 0, TOK, CHW, CHW);
}

// round 14
// speedup vs baseline: 1.1416x; 1.0085x over previous
#include <cuda_runtime.h>
#include <cuda_fp16.h>
#include <math.h>
#include <stdint.h>

#define CCH 512
#define HWT 4096
#define BATCH 2
#define NGROUPS 32
#define CPG 16

// ---------------- scratch (allocation-free) ----------------
__device__ __half  g_h[(size_t)BATCH * HWT * CCH];   // normalized, token-major
__device__ __half  g_q[(size_t)BATCH * HWT * CCH];
__device__ __half  g_k[(size_t)BATCH * HWT * CCH];
__device__ __half  g_v[(size_t)BATCH * CCH * HWT];   // channel-major
__device__ __half  g_o[(size_t)BATCH * HWT * CCH];   // attn out, token-major
__device__ __half  g_s[(size_t)BATCH * HWT * HWT];   // P = 2^(logit*log2e-5), fp16
__device__ __half  g_w[4 * CCH * CCH];               // [q_w; k_w; v_w; p_w] fp16
__device__ float2  g_part[BATCH * NGROUPS * 4];      // GN partial {sum, sumsq}

// ---------------- helpers ----------------
__device__ __forceinline__ uint32_t smem_u32(const void* p) {
    uint32_t a;
    asm("{ .reg .u64 t; cvta.to.shared.u64 t, %1; cvt.u32.u64 %0, t; }" : "=r"(a) : "l"(p));
    return a;
}
__device__ __forceinline__ void ldsm_x4(uint32_t& r0, uint32_t& r1, uint32_t& r2, uint32_t& r3,
                                        uint32_t addr) {
    asm volatile("ldmatrix.sync.aligned.m8n8.x4.shared.b16 {%0,%1,%2,%3}, [%4];"
                 : "=r"(r0), "=r"(r1), "=r"(r2), "=r"(r3) : "r"(addr));
}
__device__ __forceinline__ void mma_f16(float* c, const uint32_t* a, const uint32_t* b) {
    asm("mma.sync.aligned.m16n8k16.row.col.f32.f16.f16.f32 "
        "{%0,%1,%2,%3}, {%4,%5,%6,%7}, {%8,%9}, {%0,%1,%2,%3};"
        : "+f"(c[0]), "+f"(c[1]), "+f"(c[2]), "+f"(c[3])
        : "r"(a[0]), "r"(a[1]), "r"(a[2]), "r"(a[3]), "r"(b[0]), "r"(b[1]));
}

// ---------------- preamble: w2h (blocks 0..1023) + GN partials (1024..1279) ----------------
__global__ __launch_bounds__(256)
void preamble(const float* __restrict__ q_w, const float* __restrict__ k_w,
              const float* __restrict__ v_w, const float* __restrict__ p_w,
              __half* __restrict__ wdst,
              const float* __restrict__ x, float2* __restrict__ part) {
    const int b = blockIdx.x;
    if (b < 1024) {
        // weight fp32 -> fp16 (4 x 256K elements)
        const int i = b * 256 + threadIdx.x;
        const int N = CCH * CCH;
        wdst[i]         = __float2half_rn(q_w[i]);
        wdst[i + N]     = __float2half_rn(k_w[i]);
        wdst[i + 2 * N] = __float2half_rn(v_w[i]);
        wdst[i + 3 * N] = __float2half_rn(p_w[i]);
        return;
    }
    // GN partial sums: 256 blocks, 4 per (batch, group)
    const int pb = b - 1024;
    const int bg = pb >> 2, qt = pb & 3;
    const float4* xp = (const float4*)(x + (size_t)bg * CPG * HWT) + qt * (CPG * HWT / 16);
    const int N4 = CPG * HWT / 16;        // 4096 float4

    float s = 0.f, ss = 0.f;
    for (int i = threadIdx.x; i < N4; i += 256) {
        float4 v = xp[i];
        s  += v.x + v.y + v.z + v.w;
        ss += v.x * v.x + v.y * v.y + v.z * v.z + v.w * v.w;
    }
    __shared__ float rs[8], rss[8];
    #pragma unroll
    for (int o = 16; o > 0; o >>= 1) {
        s  += __shfl_xor_sync(~0u, s,  o);
        ss += __shfl_xor_sync(~0u, ss, o);
    }
    const int wid = threadIdx.x >> 5, lid = threadIdx.x & 31;
    if (lid == 0) { rs[wid] = s; rss[wid] = ss; }
    __syncthreads();
    if (threadIdx.x == 0) {
        float ts = 0.f, tss = 0.f;
        #pragma unroll
        for (int i = 0; i < 8; i++) { ts += rs[i]; tss += rss[i]; }
        part[pb] = make_float2(ts, tss);
    }
}

// ---------------- GN apply + transpose -> token-major fp16 h ----------------
__global__ __launch_bounds__(256)
void gn_apply_t(const float* __restrict__ x,
                const float* __restrict__ gw, const float* __restrict__ gb,
                const float2* __restrict__ part, __half* __restrict__ ht) {
    __shared__ float tile[64][65];
    __shared__ float2 stg[4];
    __shared__ float gwS[64], gbS[64];
    const int b = blockIdx.z;
    const int c0 = blockIdx.y * 64, t0 = blockIdx.x * 64;
    const float* xp = x + (size_t)b * CCH * HWT;
    __half* hp = ht + (size_t)b * HWT * CCH;
    const int tid = threadIdx.x;

    if (tid < 4) {
        const int g = b * NGROUPS + (c0 >> 4) + tid;
        float s = 0.f, ss = 0.f;
        #pragma unroll
        for (int q = 0; q < 4; q++) {
            float2 p = part[g * 4 + q];
            s += p.x; ss += p.y;
        }
        const float invN = 1.f / (float)(CPG * HWT);
        const float mean = s * invN;
        const float var  = fmaxf(ss * invN - mean * mean, 0.f);
        stg[tid] = make_float2(mean, rsqrtf(var + 1e-6f));
    }
    if (tid < 64) { gwS[tid] = gw[c0 + tid]; gbS[tid] = gb[c0 + tid]; }

    const int r = tid >> 2, q = tid & 3;
    const float4* xr = (const float4*)(xp + (size_t)(c0 + r) * HWT) + (t0 >> 2);
    #pragma unroll
    for (int i = 0; i < 4; i++) {
        float4 v = xr[q * 4 + i];
        tile[r][q * 16 + i * 4 + 0] = v.x;
        tile[r][q * 16 + i * 4 + 1] = v.y;
        tile[r][q * 16 + i * 4 + 2] = v.z;
        tile[r][q * 16 + i * 4 + 3] = v.w;
    }
    __syncthreads();

    #pragma unroll
    for (int p = 0; p < 4; p++) {
        const int tr = p * 16 + (tid >> 4);
        __half2* hrow = (__half2*)(hp + (size_t)(t0 + tr) * CCH + c0);
        #pragma unroll
        for (int qq = 0; qq < 2; qq++) {
            const int c2 = (tid & 15) + 16 * qq;
            const int cl0 = 2 * c2, cl1 = 2 * c2 + 1;
            const float2 mv0 = stg[cl0 >> 4];
            const float2 mv1 = stg[cl1 >> 4];
            const float a0 = mv0.y * gwS[cl0], b0 = gbS[cl0] - mv0.x * a0;
            const float a1 = mv1.y * gwS[cl1], b1 = gbS[cl1] - mv1.x * a1;
            hrow[c2] = __floats2half2_rn(tile[cl0][tr] * a0 + b0,
                                         tile[cl1][tr] * a1 + b1);
        }
    }
}

// ---------------- fp16 HMMA GEMM, CTA 128x128, 3-stage cp.async (R8/R13 proven) ----------------
// MODE 0: scores  -> out half2 = ex2.approx.f16x2(acc*scale*log2e - 5)
// MODE 1: qkv     -> seg by n0: q/k token-major (+bias sel), v seg smem-staged transpose
// MODE 2: attn@V  -> rowsum of A tiles, out half = acc / rowsum[m]
// MODE 3: proj    -> out float = acc + bias[m] + res[m][n]
template<int MODE>
__global__ __launch_bounds__(256, 2)
void mma_gemm(const __half* __restrict__ A, const __half* __restrict__ B,
              const float* __restrict__ bias, const float* __restrict__ bias2,
              const float* __restrict__ bias3, const float* __restrict__ res,
              void* __restrict__ outv, __half* __restrict__ outK, __half* __restrict__ outV,
              int lda, int ldb, int ldo, int K, float scale,
              size_t sA, size_t sB, size_t sO, size_t sR) {
    constexpr int STG = 16384;           // 128 rows x 128B (BK=64 fp16)
    constexpr int NSTG = 3;
    extern __shared__ char smem[];       // [A0 A1 A2 | B0 B1 B2 | rowsum]
    const uint32_t sb = smem_u32(smem);
    const uint32_t sbB = sb + NSTG * STG;
    float* rs_s = (float*)(smem + 2 * NSTG * STG);

    const int bz = blockIdx.z;
    A += (size_t)bz * sA;
    B += (size_t)bz * sB;
    if (MODE == 3) res += (size_t)bz * sR;
    if (MODE == 1) {
        outK += (size_t)bz * sO;
        outV += (size_t)bz * sO;
    }

    const int m0 = blockIdx.y * 128;
    const int n0 = blockIdx.x * 128;
    const int tid = threadIdx.x;
    const int lane = tid & 31;
    const int wid = tid >> 5;
    const int wm = wid & 1;              // 2 x 64 rows
    const int wn = wid >> 1;             // 4 x 32 cols

    // MODE 1: per-CTA bias segment select (q_b / k_b / v_b)
    const float* biasSeg = bias;
    if (MODE == 1) {
        const int seg = n0 >> 9;
        biasSeg = (seg == 0) ? bias : (seg == 1) ? bias2 : bias3;
    }

    // ---- cp.async geometry ----
    const int r0 = tid >> 3;             // 0..31
    const int cb = tid & 7;
    const __half* gA = A + (size_t)(m0 + r0) * lda + cb * 8;
    const __half* gB = B + (size_t)(n0 + r0) * ldb + cb * 8;
    uint32_t soff[4];
    #pragma unroll
    for (int it = 0; it < 4; it++) {
        const int row = r0 + 32 * it;
        soff[it] = (uint32_t)row * 128u + (uint32_t)((cb ^ (row & 7)) << 4);
    }

    // ---- ldmatrix geometry ----
    const int aRowB = wm * 64 + (lane & 15);
    const int aCk = (lane >> 4) & 1;
    const int bRowB = wn * 32 + (lane & 7) + (((lane >> 4) & 1) << 3);
    const int bCk = (lane >> 3) & 1;
    const int xr = lane & 7;

    // ---- rowsum geometry (MODE 2) ----
    const int srow = tid >> 1;           // 0..127
    const int shalf = tid & 1;
    uint32_t rsoff[4];
    if (MODE == 2) {
        #pragma unroll
        for (int c4 = 0; c4 < 4; c4++) {
            const int ch = shalf * 4 + c4;
            rsoff[c4] = (uint32_t)srow * 128u + (uint32_t)((ch ^ (srow & 7)) << 4);
        }
    }
    float rsum = 0.f;

    float acc[4][4][4];
    #pragma unroll
    for (int mi = 0; mi < 4; mi++)
        #pragma unroll
        for (int ni = 0; ni < 4; ni++)
            #pragma unroll
            for (int r = 0; r < 4; r++) acc[mi][ni][r] = 0.f;

    auto load_tile = [&](int i, int s) {
        const __half* ga = gA + (size_t)i * 64;
        const __half* gb_ = gB + (size_t)i * 64;
        const uint32_t sa = sb + s * STG;
        const uint32_t sbb = sbB + s * STG;
        #pragma unroll
        for (int it = 0; it < 4; it++)
            asm volatile("cp.async.cg.shared.global [%0], [%1], 16;"
                :: "r"(sa + soff[it]), "l"(ga + (size_t)(32 * it) * lda) : "memory");
        #pragma unroll
        for (int it = 0; it < 4; it++)
            asm volatile("cp.async.cg.shared.global [%0], [%1], 16;"
                :: "r"(sbb + soff[it]), "l"(gb_ + (size_t)(32 * it) * ldb) : "memory");
    };

    const int NT = K / 64;
    load_tile(0, 0);
    asm volatile("cp.async.commit_group;" ::: "memory");
    load_tile(1, 1);
    asm volatile("cp.async.commit_group;" ::: "memory");

    int stage = 0;
    for (int i = 0; i < NT; i++) {
        asm volatile("cp.async.wait_group %0;" :: "n"(1) : "memory");
        __syncthreads();
        if (i + 2 < NT) {
            int s2 = stage + 2; if (s2 >= NSTG) s2 -= NSTG;
            load_tile(i + 2, s2);
        }
        asm volatile("cp.async.commit_group;" ::: "memory");

        if (MODE == 2) {
            // accumulate row sums of this A tile (P values)
            const char* base = smem + stage * STG;
            #pragma unroll
            for (int c4 = 0; c4 < 4; c4++) {
                uint4 d = *(const uint4*)(base + rsoff[c4]);
                float2 f0 = __half22float2(*(__half2*)&d.x);
                float2 f1 = __half22float2(*(__half2*)&d.y);
                float2 f2 = __half22float2(*(__half2*)&d.z);
                float2 f3 = __half22float2(*(__half2*)&d.w);
                rsum += (f0.x + f0.y) + (f1.x + f1.y) + (f2.x + f2.y) + (f3.x + f3.y);
            }
        }

        const uint32_t saS = sb + stage * STG;
        const uint32_t sbS = sbB + stage * STG;
        #pragma unroll
        for (int t = 0; t < 4; t++) {
            uint32_t af[4][4], bf[4][2];
            #pragma unroll
            for (int mi = 0; mi < 4; mi++)
                ldsm_x4(af[mi][0], af[mi][1], af[mi][2], af[mi][3],
                        saS + (uint32_t)(aRowB + mi * 16) * 128u
                            + (uint32_t)(((2 * t + aCk) ^ xr) << 4));
            #pragma unroll
            for (int ni2 = 0; ni2 < 2; ni2++)
                ldsm_x4(bf[2 * ni2][0], bf[2 * ni2][1], bf[2 * ni2 + 1][0], bf[2 * ni2 + 1][1],
                        sbS + (uint32_t)(bRowB + ni2 * 16) * 128u
                            + (uint32_t)(((2 * t + bCk) ^ xr) << 4));
            #pragma unroll
            for (int mi = 0; mi < 4; mi++)
                #pragma unroll
                for (int ni = 0; ni < 4; ni++)
                    mma_f16(acc[mi][ni], af[mi], bf[ni]);
        }
        stage++; if (stage >= NSTG) stage -= NSTG;
    }

    if (MODE == 2) {
        rsum += __shfl_xor_sync(~0u, rsum, 1);
        rs_s[srow] = rsum;               // both halves write same value
        __syncthreads();
    }

    // ---- MODE 1, v segment: smem-staged transpose for coalesced stores ----
    if (MODE == 1 && (n0 >> 9) == 2) {
        asm volatile("cp.async.wait_group 0;" ::: "memory");
        __syncthreads();
        __half* st = (__half*)smem;
        constexpr int SSTR = 136;        // half stride, padded
        #pragma unroll
        for (int mi = 0; mi < 4; mi++) {
            const int rl0 = wm * 64 + mi * 16 + (lane >> 2);
            #pragma unroll
            for (int ni = 0; ni < 4; ni++) {
                const int ccl = wn * 32 + ni * 8 + 2 * (lane & 3);
                const int nc = (n0 + ccl) & (CCH - 1);
                #pragma unroll
                for (int hf = 0; hf < 2; hf++) {
                    const int rl = rl0 + hf * 8;
                    st[ccl * SSTR + rl]       = __float2half_rn(acc[mi][ni][hf * 2 + 0] + biasSeg[nc]);
                    st[(ccl + 1) * SSTR + rl] = __float2half_rn(acc[mi][ni][hf * 2 + 1] + biasSeg[nc + 1]);
                }
            }
        }
        __syncthreads();
        const int nc0 = n0 - 1024;
        #pragma unroll
        for (int p = 0; p < 8; p++) {
            const int cl = p * 16 + (tid >> 4);
            __half2* orow = (__half2*)(outV + (size_t)(nc0 + cl) * HWT + m0);
            #pragma unroll
            for (int q = 0; q < 4; q++) {
                const int t2 = (tid & 15) + 16 * q;
                orow[t2] = *(__half2*)&st[cl * SSTR + 2 * t2];
            }
        }
        return;
    }

    // ---- epilogue ----
    const float c1 = scale * 1.4426950408889634f;   // scale * log2(e)
    #pragma unroll
    for (int mi = 0; mi < 4; mi++) {
        const int rl0 = wm * 64 + mi * 16 + (lane >> 2);
        #pragma unroll
        for (int ni = 0; ni < 4; ni++) {
            const int ccg = n0 + wn * 32 + ni * 8 + 2 * (lane & 3);
            #pragma unroll
            for (int hf = 0; hf < 2; hf++) {
                const int rl = rl0 + hf * 8;
                const int r = m0 + rl;
                float vx = acc[mi][ni][hf * 2 + 0];
                float vy = acc[mi][ni][hf * 2 + 1];
                if (MODE == 0) {
                    // P = 2^(logit*log2e - 5)  via f16x2 MUFU (2 vals/op)
                    const float yx = fmaf(vx, c1, -5.0f);
                    const float yy = fmaf(vy, c1, -5.0f);
                    uint32_t h2, p2;
                    asm("cvt.rn.f16x2.f32 %0, %1, %2;" : "=r"(h2) : "f"(yy), "f"(yx));
                    asm("ex2.approx.f16x2 %0, %1;" : "=r"(p2) : "r"(h2));
                    __half* o = (__half*)outv + (size_t)bz * sO;
                    *(uint32_t*)(o + (size_t)r * ldo + ccg) = p2;
                } else if (MODE == 1) {
                    const int nc = ccg & (CCH - 1);
                    vx += biasSeg[nc]; vy += biasSeg[nc + 1];
                    __half* o = ((n0 >> 9) == 0) ? (__half*)outv + (size_t)bz * sO : outK;
                    *(__half2*)(o + (size_t)r * CCH + nc) = __floats2half2_rn(vx, vy);
                } else if (MODE == 2) {
                    const float inv = 1.f / rs_s[rl];
                    __half* o = (__half*)outv + (size_t)bz * sO;
                    *(__half2*)(o + (size_t)r * ldo + ccg) =
                        __floats2half2_rn(vx * inv, vy * inv);
                } else {
                    const float bm = bias[r];
                    float2 rr = *(const float2*)&res[(size_t)r * ldo + ccg];
                    float* o = (float*)outv + (size_t)bz * sO;
                    float2 v; v.x = vx + bm + rr.x; v.y = vy + bm + rr.y;
                    *(float2*)(o + (size_t)r * ldo + ccg) = v;
                }
            }
        }
    }
}

// ---------------- launch ----------------
extern "C" void kernel_launch(void* const* d_in, const int* in_sizes, int n_in,
                              void* d_out, int out_size) {
    const float* x    = (const float*)d_in[0];
    const float* gn_w = (const float*)d_in[1];
    const float* gn_b = (const float*)d_in[2];
    const float* q_w  = (const float*)d_in[3];
    const float* q_b  = (const float*)d_in[4];
    const float* k_w  = (const float*)d_in[5];
    const float* k_b  = (const float*)d_in[6];
    const float* v_w  = (const float*)d_in[7];
    const float* v_b  = (const float*)d_in[8];
    const float* p_w  = (const float*)d_in[9];
    const float* p_b  = (const float*)d_in[10];
    float* out = (float*)d_out;

    __half *h, *q, *k, *v, *o, *s, *w;
    float2* part;
    cudaGetSymbolAddress((void**)&h, g_h);
    cudaGetSymbolAddress((void**)&q, g_q);
    cudaGetSymbolAddress((void**)&k, g_k);
    cudaGetSymbolAddress((void**)&v, g_v);
    cudaGetSymbolAddress((void**)&o, g_o);
    cudaGetSymbolAddress((void**)&s, g_s);
    cudaGetSymbolAddress((void**)&w, g_w);
    cudaGetSymbolAddress((void**)&part, g_part);

    const int SMEM_T = 3 * 2 * 16384 + 512;   // 98816
    cudaFuncSetAttribute(mma_gemm<0>, cudaFuncAttributeMaxDynamicSharedMemorySize, SMEM_T);
    cudaFuncSetAttribute(mma_gemm<1>, cudaFuncAttributeMaxDynamicSharedMemorySize, SMEM_T);
    cudaFuncSetAttribute(mma_gemm<2>, cudaFuncAttributeMaxDynamicSharedMemorySize, SMEM_T);
    cudaFuncSetAttribute(mma_gemm<3>, cudaFuncAttributeMaxDynamicSharedMemorySize, SMEM_T);

    const size_t TOK = (size_t)HWT * CCH;
    const size_t SS  = (size_t)HWT * HWT;
    const size_t CHW = (size_t)CCH * HWT;
    const int WN = CCH * CCH;
    const float att_scale = 0.04419417382415922f; // 1/sqrt(512)

    // 0. preamble: weights -> fp16 concat  ||  GN partial sums (one launch)
    preamble<<<1024 + BATCH * NGROUPS * 4, 256>>>(q_w, k_w, v_w, p_w, w, x, part);
    __half* pw = w + 3 * WN;

    // 1. GN apply/transpose -> h token-major fp16
    gn_apply_t<<<dim3(HWT / 64, CCH / 64, BATCH), 256>>>(x, gn_w, gn_b, part, h);

    // 2. fused qkv: M=HW, N=1536, K=512; v written channel-major transposed
    dim3 gq(3 * CCH / 128, HWT / 128, BATCH);
    mma_gemm<1><<<gq, 256, SMEM_T>>>(h, w, q_b, k_b, v_b, nullptr, q, k, v,
        CCH, CCH, CCH, CCH, 1.f, TOK, 0, TOK, 0);

    // 3. P = 2^(scale*log2e * Q@K^T - 5) : M=N=HW, K=C
    dim3 gs(HWT / 128, HWT / 128, BATCH);
    mma_gemm<0><<<gs, 256, SMEM_T>>>(q, k, nullptr, nullptr, nullptr, nullptr,
        s, nullptr, nullptr,
        CCH, CCH, HWT, CCH, att_scale, TOK, TOK, SS, 0);

    // 4. o = (P@V) / rowsum(P) : M=HW, N=C, K=HW
    dim3 ga(CCH / 128, HWT / 128, BATCH);
    mma_gemm<2><<<ga, 256, SMEM_T>>>(s, v, nullptr, nullptr, nullptr, nullptr,
        o, nullptr, nullptr,
        HWT, HWT, CCH, HWT, 1.f, SS, TOK, TOK, 0);

    // 5. out = x + P_w @ o^T (channel-major): M=C, N=HW, K=C
    dim3 gp(HWT / 128, CCH / 128, BATCH);
    mma_gemm<3><<<gp, 256, SMEM_T>>>(pw, o, p_b, nullptr, nullptr, x,
        out, nullptr, nullptr,
        CCH, CCH, HWT, CCH, 1.f, 0, TOK, CHW, CHW);
}

// round 15
// speedup vs baseline: 1.1567x; 1.0132x over previous
#include <cuda_runtime.h>
#include <cuda_fp16.h>
#include <math.h>
#include <stdint.h>

#define CCH 512
#define HWT 4096
#define BATCH 2
#define NGROUPS 32
#define CPG 16

// ---------------- scratch (allocation-free) ----------------
__device__ __half  g_h[(size_t)BATCH * HWT * CCH];   // normalized, token-major
__device__ __half  g_q[(size_t)BATCH * HWT * CCH];
__device__ __half  g_k[(size_t)BATCH * HWT * CCH];
__device__ __half  g_v[(size_t)BATCH * CCH * HWT];   // channel-major
__device__ __half  g_o[(size_t)BATCH * HWT * CCH];   // attn out, token-major
__device__ __half  g_s[(size_t)BATCH * HWT * HWT];   // P = 2^(logit*log2e-5), fp16
__device__ __half  g_w[4 * CCH * CCH];               // [q_w; k_w; v_w; p_w] fp16
__device__ float2  g_part[BATCH * NGROUPS * 4];      // GN partial {sum, sumsq}

// ---------------- helpers ----------------
__device__ __forceinline__ uint32_t smem_u32(const void* p) {
    uint32_t a;
    asm("{ .reg .u64 t; cvta.to.shared.u64 t, %1; cvt.u32.u64 %0, t; }" : "=r"(a) : "l"(p));
    return a;
}
__device__ __forceinline__ void ldsm_x4(uint32_t& r0, uint32_t& r1, uint32_t& r2, uint32_t& r3,
                                        uint32_t addr) {
    asm volatile("ldmatrix.sync.aligned.m8n8.x4.shared.b16 {%0,%1,%2,%3}, [%4];"
                 : "=r"(r0), "=r"(r1), "=r"(r2), "=r"(r3) : "r"(addr));
}
__device__ __forceinline__ void mma_f16(float* c, const uint32_t* a, const uint32_t* b) {
    asm("mma.sync.aligned.m16n8k16.row.col.f32.f16.f16.f32 "
        "{%0,%1,%2,%3}, {%4,%5,%6,%7}, {%8,%9}, {%0,%1,%2,%3};"
        : "+f"(c[0]), "+f"(c[1]), "+f"(c[2]), "+f"(c[3])
        : "r"(a[0]), "r"(a[1]), "r"(a[2]), "r"(a[3]), "r"(b[0]), "r"(b[1]));
}

// ---------------- preamble: w2h (blocks 0..1023) + GN partials (1024..1279) ----------------
__global__ __launch_bounds__(256)
void preamble(const float* __restrict__ q_w, const float* __restrict__ k_w,
              const float* __restrict__ v_w, const float* __restrict__ p_w,
              __half* __restrict__ wdst,
              const float* __restrict__ x, float2* __restrict__ part) {
    const int b = blockIdx.x;
    if (b < 1024) {
        const int i = b * 256 + threadIdx.x;
        const int N = CCH * CCH;
        wdst[i]         = __float2half_rn(q_w[i]);
        wdst[i + N]     = __float2half_rn(k_w[i]);
        wdst[i + 2 * N] = __float2half_rn(v_w[i]);
        wdst[i + 3 * N] = __float2half_rn(p_w[i]);
        return;
    }
    const int pb = b - 1024;
    const int bg = pb >> 2, qt = pb & 3;
    const float4* xp = (const float4*)(x + (size_t)bg * CPG * HWT) + qt * (CPG * HWT / 16);
    const int N4 = CPG * HWT / 16;

    float s = 0.f, ss = 0.f;
    for (int i = threadIdx.x; i < N4; i += 256) {
        float4 v = xp[i];
        s  += v.x + v.y + v.z + v.w;
        ss += v.x * v.x + v.y * v.y + v.z * v.z + v.w * v.w;
    }
    __shared__ float rs[8], rss[8];
    #pragma unroll
    for (int o = 16; o > 0; o >>= 1) {
        s  += __shfl_xor_sync(~0u, s,  o);
        ss += __shfl_xor_sync(~0u, ss, o);
    }
    const int wid = threadIdx.x >> 5, lid = threadIdx.x & 31;
    if (lid == 0) { rs[wid] = s; rss[wid] = ss; }
    __syncthreads();
    if (threadIdx.x == 0) {
        float ts = 0.f, tss = 0.f;
        #pragma unroll
        for (int i = 0; i < 8; i++) { ts += rs[i]; tss += rss[i]; }
        part[pb] = make_float2(ts, tss);
    }
}

// ---------------- GN apply + transpose -> token-major fp16 h ----------------
__global__ __launch_bounds__(256)
void gn_apply_t(const float* __restrict__ x,
                const float* __restrict__ gw, const float* __restrict__ gb,
                const float2* __restrict__ part, __half* __restrict__ ht) {
    __shared__ float tile[64][65];
    __shared__ float2 stg[4];
    __shared__ float gwS[64], gbS[64];
    const int b = blockIdx.z;
    const int c0 = blockIdx.y * 64, t0 = blockIdx.x * 64;
    const float* xp = x + (size_t)b * CCH * HWT;
    __half* hp = ht + (size_t)b * HWT * CCH;
    const int tid = threadIdx.x;

    if (tid < 4) {
        const int g = b * NGROUPS + (c0 >> 4) + tid;
        float s = 0.f, ss = 0.f;
        #pragma unroll
        for (int q = 0; q < 4; q++) {
            float2 p = part[g * 4 + q];
            s += p.x; ss += p.y;
        }
        const float invN = 1.f / (float)(CPG * HWT);
        const float mean = s * invN;
        const float var  = fmaxf(ss * invN - mean * mean, 0.f);
        stg[tid] = make_float2(mean, rsqrtf(var + 1e-6f));
    }
    if (tid < 64) { gwS[tid] = gw[c0 + tid]; gbS[tid] = gb[c0 + tid]; }

    const int r = tid >> 2, q = tid & 3;
    const float4* xr = (const float4*)(xp + (size_t)(c0 + r) * HWT) + (t0 >> 2);
    #pragma unroll
    for (int i = 0; i < 4; i++) {
        float4 v = xr[q * 4 + i];
        tile[r][q * 16 + i * 4 + 0] = v.x;
        tile[r][q * 16 + i * 4 + 1] = v.y;
        tile[r][q * 16 + i * 4 + 2] = v.z;
        tile[r][q * 16 + i * 4 + 3] = v.w;
    }
    __syncthreads();

    #pragma unroll
    for (int p = 0; p < 4; p++) {
        const int tr = p * 16 + (tid >> 4);
        __half2* hrow = (__half2*)(hp + (size_t)(t0 + tr) * CCH + c0);
        #pragma unroll
        for (int qq = 0; qq < 2; qq++) {
            const int c2 = (tid & 15) + 16 * qq;
            const int cl0 = 2 * c2, cl1 = 2 * c2 + 1;
            const float2 mv0 = stg[cl0 >> 4];
            const float2 mv1 = stg[cl1 >> 4];
            const float a0 = mv0.y * gwS[cl0], b0 = gbS[cl0] - mv0.x * a0;
            const float a1 = mv1.y * gwS[cl1], b1 = gbS[cl1] - mv1.x * a1;
            hrow[c2] = __floats2half2_rn(tile[cl0][tr] * a0 + b0,
                                         tile[cl1][tr] * a1 + b1);
        }
    }
}

// ---------------- fp16 HMMA GEMM, CTA 128x128, 3-stage cp.async ----------------
// Mainloop: fragment double-buffered (ldsm for t+1 issued before mma of t).
// MODE 0: scores  -> out half2 = ex2.approx.f16x2(acc*scale*log2e - 5)
// MODE 1: qkv     -> seg by n0: q/k token-major (+bias sel), v seg smem-staged transpose
// MODE 2: attn@V  -> rowsum of A tiles, out half = acc / rowsum[m]
// MODE 3: proj    -> out float = acc + bias[m] + res[m][n]
template<int MODE>
__global__ __launch_bounds__(256, 2)
void mma_gemm(const __half* __restrict__ A, const __half* __restrict__ B,
              const float* __restrict__ bias, const float* __restrict__ bias2,
              const float* __restrict__ bias3, const float* __restrict__ res,
              void* __restrict__ outv, __half* __restrict__ outK, __half* __restrict__ outV,
              int lda, int ldb, int ldo, int K, float scale,
              size_t sA, size_t sB, size_t sO, size_t sR) {
    constexpr int STG = 16384;           // 128 rows x 128B (BK=64 fp16)
    constexpr int NSTG = 3;
    extern __shared__ char smem[];       // [A0 A1 A2 | B0 B1 B2 | rowsum]
    const uint32_t sb = smem_u32(smem);
    const uint32_t sbB = sb + NSTG * STG;
    float* rs_s = (float*)(smem + 2 * NSTG * STG);

    const int bz = blockIdx.z;
    A += (size_t)bz * sA;
    B += (size_t)bz * sB;
    if (MODE == 3) res += (size_t)bz * sR;
    if (MODE == 1) {
        outK += (size_t)bz * sO;
        outV += (size_t)bz * sO;
    }

    const int m0 = blockIdx.y * 128;
    const int n0 = blockIdx.x * 128;
    const int tid = threadIdx.x;
    const int lane = tid & 31;
    const int wid = tid >> 5;
    const int wm = wid & 1;              // 2 x 64 rows
    const int wn = wid >> 1;             // 4 x 32 cols

    const float* biasSeg = bias;
    if (MODE == 1) {
        const int seg = n0 >> 9;
        biasSeg = (seg == 0) ? bias : (seg == 1) ? bias2 : bias3;
    }

    // ---- cp.async geometry ----
    const int r0 = tid >> 3;             // 0..31
    const int cb = tid & 7;
    const __half* gA = A + (size_t)(m0 + r0) * lda + cb * 8;
    const __half* gB = B + (size_t)(n0 + r0) * ldb + cb * 8;
    uint32_t soff[4];
    #pragma unroll
    for (int it = 0; it < 4; it++) {
        const int row = r0 + 32 * it;
        soff[it] = (uint32_t)row * 128u + (uint32_t)((cb ^ (row & 7)) << 4);
    }

    // ---- ldmatrix geometry ----
    const int aRowB = wm * 64 + (lane & 15);
    const int aCk = (lane >> 4) & 1;
    const int bRowB = wn * 32 + (lane & 7) + (((lane >> 4) & 1) << 3);
    const int bCk = (lane >> 3) & 1;
    const int xr = lane & 7;

    // ---- rowsum geometry (MODE 2) ----
    const int srow = tid >> 1;           // 0..127
    const int shalf = tid & 1;
    uint32_t rsoff[4];
    if (MODE == 2) {
        #pragma unroll
        for (int c4 = 0; c4 < 4; c4++) {
            const int ch = shalf * 4 + c4;
            rsoff[c4] = (uint32_t)srow * 128u + (uint32_t)((ch ^ (srow & 7)) << 4);
        }
    }
    float rsum = 0.f;

    float acc[4][4][4];
    #pragma unroll
    for (int mi = 0; mi < 4; mi++)
        #pragma unroll
        for (int ni = 0; ni < 4; ni++)
            #pragma unroll
            for (int r = 0; r < 4; r++) acc[mi][ni][r] = 0.f;

    auto load_tile = [&](int i, int s) {
        const __half* ga = gA + (size_t)i * 64;
        const __half* gb_ = gB + (size_t)i * 64;
        const uint32_t sa = sb + s * STG;
        const uint32_t sbb = sbB + s * STG;
        #pragma unroll
        for (int it = 0; it < 4; it++)
            asm volatile("cp.async.cg.shared.global [%0], [%1], 16;"
                :: "r"(sa + soff[it]), "l"(ga + (size_t)(32 * it) * lda) : "memory");
        #pragma unroll
        for (int it = 0; it < 4; it++)
            asm volatile("cp.async.cg.shared.global [%0], [%1], 16;"
                :: "r"(sbb + soff[it]), "l"(gb_ + (size_t)(32 * it) * ldb) : "memory");
    };

    const int NT = K / 64;
    load_tile(0, 0);
    asm volatile("cp.async.commit_group;" ::: "memory");
    load_tile(1, 1);
    asm volatile("cp.async.commit_group;" ::: "memory");

    uint32_t af[2][4][4], bf[2][4][2];

    int stage = 0;
    for (int i = 0; i < NT; i++) {
        asm volatile("cp.async.wait_group %0;" :: "n"(1) : "memory");
        __syncthreads();
        if (i + 2 < NT) {
            int s2 = stage + 2; if (s2 >= NSTG) s2 -= NSTG;
            load_tile(i + 2, s2);
        }
        asm volatile("cp.async.commit_group;" ::: "memory");

        if (MODE == 2) {
            const char* base = smem + stage * STG;
            #pragma unroll
            for (int c4 = 0; c4 < 4; c4++) {
                uint4 d = *(const uint4*)(base + rsoff[c4]);
                float2 f0 = __half22float2(*(__half2*)&d.x);
                float2 f1 = __half22float2(*(__half2*)&d.y);
                float2 f2 = __half22float2(*(__half2*)&d.z);
                float2 f3 = __half22float2(*(__half2*)&d.w);
                rsum += (f0.x + f0.y) + (f1.x + f1.y) + (f2.x + f2.y) + (f3.x + f3.y);
            }
        }

        const uint32_t saS = sb + stage * STG;
        const uint32_t sbS = sbB + stage * STG;

        // fragment prologue: load t=0 into buffer 0
        #pragma unroll
        for (int mi = 0; mi < 4; mi++)
            ldsm_x4(af[0][mi][0], af[0][mi][1], af[0][mi][2], af[0][mi][3],
                    saS + (uint32_t)(aRowB + mi * 16) * 128u
                        + (uint32_t)((aCk ^ xr) << 4));
        #pragma unroll
        for (int ni2 = 0; ni2 < 2; ni2++)
            ldsm_x4(bf[0][2 * ni2][0], bf[0][2 * ni2][1],
                    bf[0][2 * ni2 + 1][0], bf[0][2 * ni2 + 1][1],
                    sbS + (uint32_t)(bRowB + ni2 * 16) * 128u
                        + (uint32_t)((bCk ^ xr) << 4));

        #pragma unroll
        for (int t = 0; t < 4; t++) {
            const int cur = t & 1, nxt = cur ^ 1;
            if (t < 3) {
                // prefetch fragments for t+1 before the mma block
                #pragma unroll
                for (int mi = 0; mi < 4; mi++)
                    ldsm_x4(af[nxt][mi][0], af[nxt][mi][1], af[nxt][mi][2], af[nxt][mi][3],
                            saS + (uint32_t)(aRowB + mi * 16) * 128u
                                + (uint32_t)(((2 * (t + 1) + aCk) ^ xr) << 4));
                #pragma unroll
                for (int ni2 = 0; ni2 < 2; ni2++)
                    ldsm_x4(bf[nxt][2 * ni2][0], bf[nxt][2 * ni2][1],
                            bf[nxt][2 * ni2 + 1][0], bf[nxt][2 * ni2 + 1][1],
                            sbS + (uint32_t)(bRowB + ni2 * 16) * 128u
                                + (uint32_t)(((2 * (t + 1) + bCk) ^ xr) << 4));
            }
            #pragma unroll
            for (int mi = 0; mi < 4; mi++)
                #pragma unroll
                for (int ni = 0; ni < 4; ni++)
                    mma_f16(acc[mi][ni], af[cur][mi], bf[cur][ni]);
        }
        stage++; if (stage >= NSTG) stage -= NSTG;
    }

    if (MODE == 2) {
        rsum += __shfl_xor_sync(~0u, rsum, 1);
        rs_s[srow] = rsum;
        __syncthreads();
    }

    // ---- MODE 1, v segment: smem-staged transpose for coalesced stores ----
    if (MODE == 1 && (n0 >> 9) == 2) {
        asm volatile("cp.async.wait_group 0;" ::: "memory");
        __syncthreads();
        __half* st = (__half*)smem;
        constexpr int SSTR = 136;        // half stride, padded
        #pragma unroll
        for (int mi = 0; mi < 4; mi++) {
            const int rl0 = wm * 64 + mi * 16 + (lane >> 2);
            #pragma unroll
            for (int ni = 0; ni < 4; ni++) {
                const int ccl = wn * 32 + ni * 8 + 2 * (lane & 3);
                const int nc = (n0 + ccl) & (CCH - 1);
                #pragma unroll
                for (int hf = 0; hf < 2; hf++) {
                    const int rl = rl0 + hf * 8;
                    st[ccl * SSTR + rl]       = __float2half_rn(acc[mi][ni][hf * 2 + 0] + biasSeg[nc]);
                    st[(ccl + 1) * SSTR + rl] = __float2half_rn(acc[mi][ni][hf * 2 + 1] + biasSeg[nc + 1]);
                }
            }
        }
        __syncthreads();
        const int nc0 = n0 - 1024;
        #pragma unroll
        for (int p = 0; p < 8; p++) {
            const int cl = p * 16 + (tid >> 4);
            __half2* orow = (__half2*)(outV + (size_t)(nc0 + cl) * HWT + m0);
            #pragma unroll
            for (int q = 0; q < 4; q++) {
                const int t2 = (tid & 15) + 16 * q;
                orow[t2] = *(__half2*)&st[cl * SSTR + 2 * t2];
            }
        }
        return;
    }

    // ---- epilogue ----
    const float c1 = scale * 1.4426950408889634f;   // scale * log2(e)
    #pragma unroll
    for (int mi = 0; mi < 4; mi++) {
        const int rl0 = wm * 64 + mi * 16 + (lane >> 2);
        #pragma unroll
        for (int ni = 0; ni < 4; ni++) {
            const int ccg = n0 + wn * 32 + ni * 8 + 2 * (lane & 3);
            #pragma unroll
            for (int hf = 0; hf < 2; hf++) {
                const int rl = rl0 + hf * 8;
                const int r = m0 + rl;
                float vx = acc[mi][ni][hf * 2 + 0];
                float vy = acc[mi][ni][hf * 2 + 1];
                if (MODE == 0) {
                    const float yx = fmaf(vx, c1, -5.0f);
                    const float yy = fmaf(vy, c1, -5.0f);
                    uint32_t h2, p2;
                    asm("cvt.rn.f16x2.f32 %0, %1, %2;" : "=r"(h2) : "f"(yy), "f"(yx));
                    asm("ex2.approx.f16x2 %0, %1;" : "=r"(p2) : "r"(h2));
                    __half* o = (__half*)outv + (size_t)bz * sO;
                    *(uint32_t*)(o + (size_t)r * ldo + ccg) = p2;
                } else if (MODE == 1) {
                    const int nc = ccg & (CCH - 1);
                    vx += biasSeg[nc]; vy += biasSeg[nc + 1];
                    __half* o = ((n0 >> 9) == 0) ? (__half*)outv + (size_t)bz * sO : outK;
                    *(__half2*)(o + (size_t)r * CCH + nc) = __floats2half2_rn(vx, vy);
                } else if (MODE == 2) {
                    const float inv = 1.f / rs_s[rl];
                    __half* o = (__half*)outv + (size_t)bz * sO;
                    *(__half2*)(o + (size_t)r * ldo + ccg) =
                        __floats2half2_rn(vx * inv, vy * inv);
                } else {
                    const float bm = bias[r];
                    float2 rr = *(const float2*)&res[(size_t)r * ldo + ccg];
                    float* o = (float*)outv + (size_t)bz * sO;
                    float2 v; v.x = vx + bm + rr.x; v.y = vy + bm + rr.y;
                    *(float2*)(o + (size_t)r * ldo + ccg) = v;
                }
            }
        }
    }
}

// ---------------- launch ----------------
extern "C" void kernel_launch(void* const* d_in, const int* in_sizes, int n_in,
                              void* d_out, int out_size) {
    const float* x    = (const float*)d_in[0];
    const float* gn_w = (const float*)d_in[1];
    const float* gn_b = (const float*)d_in[2];
    const float* q_w  = (const float*)d_in[3];
    const float* q_b  = (const float*)d_in[4];
    const float* k_w  = (const float*)d_in[5];
    const float* k_b  = (const float*)d_in[6];
    const float* v_w  = (const float*)d_in[7];
    const float* v_b  = (const float*)d_in[8];
    const float* p_w  = (const float*)d_in[9];
    const float* p_b  = (const float*)d_in[10];
    float* out = (float*)d_out;

    __half *h, *q, *k, *v, *o, *s, *w;
    float2* part;
    cudaGetSymbolAddress((void**)&h, g_h);
    cudaGetSymbolAddress((void**)&q, g_q);
    cudaGetSymbolAddress((void**)&k, g_k);
    cudaGetSymbolAddress((void**)&v, g_v);
    cudaGetSymbolAddress((void**)&o, g_o);
    cudaGetSymbolAddress((void**)&s, g_s);
    cudaGetSymbolAddress((void**)&w, g_w);
    cudaGetSymbolAddress((void**)&part, g_part);

    const int SMEM_T = 3 * 2 * 16384 + 512;   // 98816
    cudaFuncSetAttribute(mma_gemm<0>, cudaFuncAttributeMaxDynamicSharedMemorySize, SMEM_T);
    cudaFuncSetAttribute(mma_gemm<1>, cudaFuncAttributeMaxDynamicSharedMemorySize, SMEM_T);
    cudaFuncSetAttribute(mma_gemm<2>, cudaFuncAttributeMaxDynamicSharedMemorySize, SMEM_T);
    cudaFuncSetAttribute(mma_gemm<3>, cudaFuncAttributeMaxDynamicSharedMemorySize, SMEM_T);

    const size_t TOK = (size_t)HWT * CCH;
    const size_t SS  = (size_t)HWT * HWT;
    const size_t CHW = (size_t)CCH * HWT;
    const int WN = CCH * CCH;
    const float att_scale = 0.04419417382415922f; // 1/sqrt(512)

    // 0. preamble: weights -> fp16 concat  ||  GN partial sums (one launch)
    preamble<<<1024 + BATCH * NGROUPS * 4, 256>>>(q_w, k_w, v_w, p_w, w, x, part);
    __half* pw = w + 3 * WN;

    // 1. GN apply/transpose -> h token-major fp16
    gn_apply_t<<<dim3(HWT / 64, CCH / 64, BATCH), 256>>>(x, gn_w, gn_b, part, h);

    // 2. fused qkv: M=HW, N=1536, K=512; v written channel-major transposed
    dim3 gq(3 * CCH / 128, HWT / 128, BATCH);
    mma_gemm<1><<<gq, 256, SMEM_T>>>(h, w, q_b, k_b, v_b, nullptr, q, k, v,
        CCH, CCH, CCH, CCH, 1.f, TOK, 0, TOK, 0);

    // 3. P = 2^(scale*log2e * Q@K^T - 5) : M=N=HW, K=C
    dim3 gs(HWT / 128, HWT / 128, BATCH);
    mma_gemm<0><<<gs, 256, SMEM_T>>>(q, k, nullptr, nullptr, nullptr, nullptr,
        s, nullptr, nullptr,
        CCH, CCH, HWT, CCH, att_scale, TOK, TOK, SS, 0);

    // 4. o = (P@V) / rowsum(P) : M=HW, N=C, K=HW
    dim3 ga(CCH / 128, HWT / 128, BATCH);
    mma_gemm<2><<<ga, 256, SMEM_T>>>(s, v, nullptr, nullptr, nullptr, nullptr,
        o, nullptr, nullptr,
        HWT, HWT, CCH, HWT, 1.f, SS, TOK, TOK, 0);

    // 5. out = x + P_w @ o^T (channel-major): M=C, N=HW, K=C
    dim3 gp(HWT / 128, CCH / 128, BATCH);
    mma_gemm<3><<<gp, 256, SMEM_T>>>(pw, o, p_b, nullptr, nullptr, x,
        out, nullptr, nullptr,
        CCH, CCH, HWT, CCH, 1.f, 0, TOK, CHW, CHW);
}